// round 3
// baseline (speedup 1.0000x reference)
#include <cuda_runtime.h>
#include <math.h>

#define Bx 64
#define Tt 512
#define Hh 512
#define Gg 2048
#define NCTA 128
#define REC_THREADS 256
#define REC_SMEM_FLOATS (512*72 + 512*16 + 16*64 + 4*64)
#define REC_SMEM_BYTES (REC_SMEM_FLOATS * 4)

// ---------------- device scratch (static; no runtime allocation) ----------------
__device__ float g_inp[Tt * Bx * Hh];      // [t][b][h]  current layer input / h_seq accumulator
__device__ float g_xW[Tt * Bx * Gg];       // [t][b][4H] input projection for current layer
__device__ float g_hT[Hh * Bx];            // h transposed: [k][b] for broadcast-friendly loads
__device__ float g_firsth[Bx * Hh];        // final h of layer 0 (for states output)
__device__ unsigned g_bar;                 // grid barrier counter (monotonic per layer)

// ---------------- small helpers ----------------
__device__ __forceinline__ float sigmf(float x) { return 1.f / (1.f + __expf(-x)); }

// ---------------- transpose x [B,T,H] -> g_inp [T,B,H] ----------------
__global__ void k_transpose_in(const float* __restrict__ x) {
    int t = blockIdx.x, b = blockIdx.y;
    const float4* src = (const float4*)(x + ((size_t)b * Tt + t) * Hh);
    float4* dst = (float4*)(g_inp + ((size_t)t * Bx + b) * Hh);
    dst[threadIdx.x] = src[threadIdx.x];
}

// ---------------- g_inp [T,B,H] -> out [B,T,H] ----------------
__global__ void k_output(float* __restrict__ out) {
    int t = blockIdx.x, b = blockIdx.y;
    const float4* src = (const float4*)(g_inp + ((size_t)t * Bx + b) * Hh);
    float4* dst = (float4*)(out + ((size_t)b * Tt + t) * Hh);
    dst[threadIdx.x] = src[threadIdx.x];
}

// ---------------- states: broadcast layer-0 final h to [L,B,H] ----------------
__global__ void k_states(float* __restrict__ out) {
    int b = blockIdx.x;
    float4 v = ((const float4*)(g_firsth + (size_t)b * Hh))[threadIdx.x];
    size_t base = (size_t)Bx * Tt * Hh;
#pragma unroll
    for (int l = 0; l < 4; ++l)
        ((float4*)(out + base + ((size_t)l * Bx + b) * Hh))[threadIdx.x] = v;
}

// ---------------- per-layer reset: barrier counter + h0 = 0 ----------------
__global__ void k_init() {
    if (threadIdx.x == 0) g_bar = 0u;
    for (int i = threadIdx.x; i < Hh * Bx; i += blockDim.x) g_hT[i] = 0.f;
}

// ---------------- input GEMM: g_xW = g_inp @ W + bias ----------------
// M=32768 (t*64+b), K=512, N=2048. 128x128 tile, BK=8, 256 threads, 8x8 microtile.
__global__ void __launch_bounds__(256) k_gemm(const float* __restrict__ Bm,
                                              const float* __restrict__ bias) {
    __shared__ float As[8 * 132];  // transposed A tile, padded
    __shared__ float Bs[8 * 128];

    int tid = threadIdx.x;
    int n0 = blockIdx.x * 128;
    int m0 = blockIdx.y * 128;

    int am = tid >> 1, ak = (tid & 1) * 4;
    int bk = tid >> 5, bn = (tid & 31) * 4;
    int ty = tid >> 4, tx = tid & 15;

    float acc[8][8];
#pragma unroll
    for (int i = 0; i < 8; i++)
#pragma unroll
        for (int j = 0; j < 8; j++) acc[i][j] = 0.f;

    for (int k0 = 0; k0 < 512; k0 += 8) {
        float4 a4 = *(const float4*)(g_inp + ((size_t)(m0 + am)) * 512 + k0 + ak);
        float4 b4 = *(const float4*)(Bm + ((size_t)(k0 + bk)) * 2048 + n0 + bn);
        As[(ak + 0) * 132 + am] = a4.x;
        As[(ak + 1) * 132 + am] = a4.y;
        As[(ak + 2) * 132 + am] = a4.z;
        As[(ak + 3) * 132 + am] = a4.w;
        *(float4*)(Bs + bk * 128 + bn) = b4;
        __syncthreads();
#pragma unroll
        for (int kk = 0; kk < 8; ++kk) {
            float4 a0 = *(float4*)(As + kk * 132 + ty * 8);
            float4 a1 = *(float4*)(As + kk * 132 + ty * 8 + 4);
            float4 b0 = *(float4*)(Bs + kk * 128 + tx * 8);
            float4 b1 = *(float4*)(Bs + kk * 128 + tx * 8 + 4);
            float av[8] = {a0.x, a0.y, a0.z, a0.w, a1.x, a1.y, a1.z, a1.w};
            float bv[8] = {b0.x, b0.y, b0.z, b0.w, b1.x, b1.y, b1.z, b1.w};
#pragma unroll
            for (int i = 0; i < 8; i++)
#pragma unroll
                for (int j = 0; j < 8; j++) acc[i][j] += av[i] * bv[j];
        }
        __syncthreads();
    }

    float bb[8];
#pragma unroll
    for (int j = 0; j < 8; j++) bb[j] = bias[n0 + tx * 8 + j];
#pragma unroll
    for (int i = 0; i < 8; i++) {
        float* dst = g_xW + ((size_t)(m0 + ty * 8 + i)) * 2048 + n0 + tx * 8;
        float4 v0 = make_float4(acc[i][0] + bb[0], acc[i][1] + bb[1],
                                acc[i][2] + bb[2], acc[i][3] + bb[3]);
        float4 v1 = make_float4(acc[i][4] + bb[4], acc[i][5] + bb[5],
                                acc[i][6] + bb[6], acc[i][7] + bb[7]);
        *(float4*)dst = v0;
        *(float4*)(dst + 4) = v1;
    }
}

// ---------------- persistent recurrence kernel ----------------
// 128 CTAs (1/SM), each owns 4 h-columns -> 16 z-columns (4 gates x 4 n).
// U slice (512x16) and cell state c stay in SMEM for the whole layer.
// Per step: broadcast-load h [512][64] from L2, z = h@U (k-split x4) + xW,
// gates, write h back (transposed) + h_seq (+residual), grid barrier.
__global__ void __launch_bounds__(REC_THREADS) k_lstm(const float* __restrict__ Ul, int layer) {
    extern __shared__ float sm[];
    float* h_s = sm;                    // [512][72] padded (147456 B)
    float* U_s = sm + 512 * 72;         // [512][16]
    float* z_s = U_s + 512 * 16;        // [16][64]
    float* c_s = z_s + 16 * 64;         // [4][64]
    float* scr = sm;                    // reduction scratch, aliases h_s (16 KB)

    int tid = threadIdx.x;
    int n0 = blockIdx.x * 4;

    // Load U slice once: column c = g*4+nn  <->  global column g*512 + n0 + nn
    for (int idx = tid; idx < 512 * 16; idx += REC_THREADS) {
        int k = idx >> 4, c = idx & 15;
        int g = c >> 2, nn = c & 3;
        U_s[idx] = Ul[(size_t)k * 2048 + g * 512 + n0 + nn];
    }
    c_s[tid] = (tid < 256) ? 0.f : 0.f;  // 4*64 = 256 == REC_THREADS
    __syncthreads();

    // MM decomposition: 4 k-splits x 16 b-tiles x 4 c-tiles
    int ks = tid >> 6;
    int r = tid & 63;
    int b0 = (r >> 2) * 4;
    int c0 = (r & 3) * 4;
    int kbase = ks * 128;

    int gb = tid >> 2, gg = tid & 3;    // xW phase: (batch, gate)
    int pb = tid & 63, pn = tid >> 6;   // gate phase: (batch, nn)

    for (int t = 0; t < Tt; ++t) {
        // broadcast-load h (zeros at t=0 via k_init)
        for (int idx = tid; idx < 512 * 16; idx += REC_THREADS) {
            int k = idx >> 4;
            int b4 = (idx & 15) << 2;
            *(float4*)(h_s + k * 72 + b4) = *(const float4*)(g_hT + k * 64 + b4);
        }
        __syncthreads();

        float acc[4][4];
#pragma unroll
        for (int i = 0; i < 4; i++)
#pragma unroll
            for (int j = 0; j < 4; j++) acc[i][j] = 0.f;

#pragma unroll 4
        for (int k = kbase; k < kbase + 128; ++k) {
            float4 hv = *(float4*)(h_s + k * 72 + b0);
            float4 uv = *(float4*)(U_s + k * 16 + c0);
            acc[0][0] += hv.x * uv.x; acc[0][1] += hv.x * uv.y;
            acc[0][2] += hv.x * uv.z; acc[0][3] += hv.x * uv.w;
            acc[1][0] += hv.y * uv.x; acc[1][1] += hv.y * uv.y;
            acc[1][2] += hv.y * uv.z; acc[1][3] += hv.y * uv.w;
            acc[2][0] += hv.z * uv.x; acc[2][1] += hv.z * uv.y;
            acc[2][2] += hv.z * uv.z; acc[2][3] += hv.z * uv.w;
            acc[3][0] += hv.w * uv.x; acc[3][1] += hv.w * uv.y;
            acc[3][2] += hv.w * uv.z; acc[3][3] += hv.w * uv.w;
        }
        __syncthreads();  // all h_s reads done before scr (alias) is written

        float* ms = scr + tid * 16;
#pragma unroll
        for (int i = 0; i < 4; i++)
#pragma unroll
            for (int j = 0; j < 4; j++) ms[i * 4 + j] = acc[i][j];
        __syncthreads();

        // reduce 4 k-splits -> z_s[c][b]
        for (int e = tid; e < 1024; e += REC_THREADS) {
            int c = e >> 6, b = e & 63;
            int src = ((b >> 2) << 2) + (c >> 2);
            int ai = ((b & 3) << 2) + (c & 3);
            float s = scr[src * 16 + ai] + scr[(src + 64) * 16 + ai] +
                      scr[(src + 128) * 16 + ai] + scr[(src + 192) * 16 + ai];
            z_s[c * 64 + b] = s;
        }
        __syncthreads();

        // add xW (coalesced float4 per (batch, gate))
        {
            float4 xw = *(const float4*)(g_xW + ((size_t)t * 64 + gb) * 2048 + gg * 512 + n0);
            z_s[(gg * 4 + 0) * 64 + gb] += xw.x;
            z_s[(gg * 4 + 1) * 64 + gb] += xw.y;
            z_s[(gg * 4 + 2) * 64 + gb] += xw.z;
            z_s[(gg * 4 + 3) * 64 + gb] += xw.w;
        }
        __syncthreads();

        // gates + state update
        {
            float zi = z_s[(0 + pn) * 64 + pb];
            float zf = z_s[(4 + pn) * 64 + pb];
            float zg = z_s[(8 + pn) * 64 + pb];
            float zo = z_s[(12 + pn) * 64 + pb];
            float cp = c_s[pn * 64 + pb];
            float cn = sigmf(zf) * cp + sigmf(zi) * tanhf(zg);
            float hh = sigmf(zo) * tanhf(cn);
            c_s[pn * 64 + pb] = cn;
            g_hT[(n0 + pn) * 64 + pb] = hh;
            size_t io = ((size_t)t * 64 + pb) * 512 + n0 + pn;
            if (layer == 0) g_inp[io] = hh;
            else            g_inp[io] += hh;
            if (layer == 0 && t == Tt - 1) g_firsth[(size_t)pb * 512 + n0 + pn] = hh;
        }

        // grid barrier (monotonic counter; reset per layer by k_init)
        __threadfence();
        __syncthreads();
        if (tid == 0) {
            atomicAdd(&g_bar, 1u);
            unsigned target = (unsigned)(t + 1) * NCTA;
            while (*((volatile unsigned*)&g_bar) < target) { }
            __threadfence();  // invalidate L1 so fresh g_hT is visible
        }
        __syncthreads();
    }
}

// ---------------- launch ----------------
extern "C" void kernel_launch(void* const* d_in, const int* in_sizes, int n_in,
                              void* d_out, int out_size) {
    const float* x    = (const float*)d_in[0];
    const float* W    = (const float*)d_in[1];
    const float* U    = (const float*)d_in[2];
    const float* bias = (const float*)d_in[3];
    float* out = (float*)d_out;

    cudaFuncSetAttribute(k_lstm, cudaFuncAttributeMaxDynamicSharedMemorySize, REC_SMEM_BYTES);

    k_transpose_in<<<dim3(Tt, Bx), 128>>>(x);

    for (int l = 0; l < 4; ++l) {
        k_init<<<1, 256>>>();
        dim3 gg(Gg / 128, (Tt * Bx) / 128);
        k_gemm<<<gg, 256>>>(W + (size_t)l * Hh * Gg, bias + (size_t)l * Gg);
        k_lstm<<<NCTA, REC_THREADS, REC_SMEM_BYTES>>>(U + (size_t)l * Hh * Gg, l);
    }

    k_output<<<dim3(Tt, Bx), 128>>>(out);
    k_states<<<Bx, 128>>>(out);
}

// round 6
// speedup vs baseline: 1.1072x; 1.1072x over previous
#include <cuda_runtime.h>
#include <cuda_bf16.h>
#include <math.h>

typedef unsigned int u32;
typedef unsigned long long u64;

#define Bx 64
#define Tt 512
#define Hh 512
#define Gg 2048
#define NCTA_R 64

// ---------------- device scratch ----------------
__device__ float g_inp[Tt * Bx * Hh];          // [t][b][h] layer input / residual accumulator
__device__ float g_xW[Tt * Bx * Gg];           // [t][b][4H]
__device__ __nv_bfloat16 g_A_hi[Tt * Bx * Hh]; // split of g_inp
__device__ __nv_bfloat16 g_A_lo[Tt * Bx * Hh];
__device__ __nv_bfloat16 g_W_hi[Hh * Gg];      // split of W (natural [k][n])
__device__ __nv_bfloat16 g_W_lo[Hh * Gg];
__device__ __nv_bfloat16 g_h_hi[Bx * Hh];      // h split, [b][k]
__device__ __nv_bfloat16 g_h_lo[Bx * Hh];
__device__ float g_firsth[Bx * Hh];
__device__ unsigned g_bar;

// ---------------- helpers ----------------
__device__ __forceinline__ u32 smem_u32(const void* p) {
    u32 a;
    asm("{ .reg .u64 t; cvta.to.shared.u64 t, %1; cvt.u32.u64 %0, t; }" : "=r"(a) : "l"(p));
    return a;
}
__device__ __forceinline__ void ldsm4(u32& r0, u32& r1, u32& r2, u32& r3, u32 a) {
    asm volatile("ldmatrix.sync.aligned.m8n8.x4.shared.b16 {%0,%1,%2,%3}, [%4];"
                 : "=r"(r0), "=r"(r1), "=r"(r2), "=r"(r3) : "r"(a));
}
__device__ __forceinline__ void ldsm4t(u32& r0, u32& r1, u32& r2, u32& r3, u32 a) {
    asm volatile("ldmatrix.sync.aligned.m8n8.x4.trans.shared.b16 {%0,%1,%2,%3}, [%4];"
                 : "=r"(r0), "=r"(r1), "=r"(r2), "=r"(r3) : "r"(a));
}
__device__ __forceinline__ void mma_bf16(float* c, const u32* a, const u32* b) {
    asm volatile("mma.sync.aligned.m16n8k16.row.col.f32.bf16.bf16.f32 "
                 "{%0,%1,%2,%3}, {%4,%5,%6,%7}, {%8,%9}, {%0,%1,%2,%3};"
                 : "+f"(c[0]), "+f"(c[1]), "+f"(c[2]), "+f"(c[3])
                 : "r"(a[0]), "r"(a[1]), "r"(a[2]), "r"(a[3]), "r"(b[0]), "r"(b[1]));
}
#define CP16(dst, src) asm volatile("cp.async.cg.shared.global [%0], [%1], 16;" :: "r"(dst), "l"(src) : "memory")
#define CPCOMMIT()     asm volatile("cp.async.commit_group;" ::: "memory")
#define CPWAIT0()      asm volatile("cp.async.wait_group 0;" ::: "memory")
#define CPWAIT1()      asm volatile("cp.async.wait_group 1;" ::: "memory")

__device__ __forceinline__ float sigmf(float x) { return 1.f / (1.f + __expf(-x)); }

__device__ __forceinline__ void split8(float4 f0, float4 f1, uint4& hv, uint4& lv) {
    float f[8] = {f0.x, f0.y, f0.z, f0.w, f1.x, f1.y, f1.z, f1.w};
    __nv_bfloat16 h[8], l[8];
#pragma unroll
    for (int i = 0; i < 8; ++i) {
        h[i] = __float2bfloat16_rn(f[i]);
        l[i] = __float2bfloat16_rn(f[i] - __bfloat162float(h[i]));
    }
    hv = *reinterpret_cast<uint4*>(h);
    lv = *reinterpret_cast<uint4*>(l);
}

// ---------------- transpose / output / states / init / splits ----------------
__global__ void k_transpose_in(const float* __restrict__ x) {
    int t = blockIdx.x, b = blockIdx.y;
    const float4* src = (const float4*)(x + ((size_t)b * Tt + t) * Hh);
    float4* dst = (float4*)(g_inp + ((size_t)t * Bx + b) * Hh);
    dst[threadIdx.x] = src[threadIdx.x];
}
__global__ void k_output(float* __restrict__ out) {
    int t = blockIdx.x, b = blockIdx.y;
    const float4* src = (const float4*)(g_inp + ((size_t)t * Bx + b) * Hh);
    float4* dst = (float4*)(out + ((size_t)b * Tt + t) * Hh);
    dst[threadIdx.x] = src[threadIdx.x];
}
__global__ void k_states(float* __restrict__ out) {
    int b = blockIdx.x;
    float4 v = ((const float4*)(g_firsth + (size_t)b * Hh))[threadIdx.x];
    size_t base = (size_t)Bx * Tt * Hh;
#pragma unroll
    for (int l = 0; l < 4; ++l)
        ((float4*)(out + base + ((size_t)l * Bx + b) * Hh))[threadIdx.x] = v;
}
__global__ void k_init() {
    if (blockIdx.x == 0 && threadIdx.x == 0) g_bar = 0u;
    int idx = blockIdx.x * 256 + threadIdx.x;  // 4096 uint4 per array
    ((uint4*)g_h_hi)[idx] = make_uint4(0, 0, 0, 0);
    ((uint4*)g_h_lo)[idx] = make_uint4(0, 0, 0, 0);
}
__global__ void k_split_inp() {
    size_t i8 = ((size_t)blockIdx.x * 256 + threadIdx.x) * 8;
    float4 f0 = *(const float4*)(g_inp + i8);
    float4 f1 = *(const float4*)(g_inp + i8 + 4);
    uint4 hv, lv;
    split8(f0, f1, hv, lv);
    *(uint4*)(g_A_hi + i8) = hv;
    *(uint4*)(g_A_lo + i8) = lv;
}
__global__ void k_split_W(const float* __restrict__ Wl) {
    size_t i8 = ((size_t)blockIdx.x * 256 + threadIdx.x) * 8;
    float4 f0 = __ldg((const float4*)(Wl + i8));
    float4 f1 = __ldg((const float4*)(Wl + i8 + 4));
    uint4 hv, lv;
    split8(f0, f1, hv, lv);
    *(uint4*)(g_W_hi + i8) = hv;
    *(uint4*)(g_W_lo + i8) = lv;
}

// ---------------- input GEMM: g_xW = g_inp @ W + bias (split-bf16 HMMA) ----------------
// BM=128, BN=128, BK=64, virtual K = 1536 (Ah@Wh, Ah@Wl, Al@Wh).
// 8 warps = 2(m64) x 4(n32). Double-buffered cp.async staging.
// SMEM: A stage 128 rows x 72 elems (144B), B stage 64 rows x 136 elems (272B).
#define GA_OFF(buf) ((buf) * 18432)
#define GB_OFF(buf) (36864 + (buf) * 17408)
#define GEMM_SMEM 71680

__global__ void __launch_bounds__(256) k_gemm_tc(const float* __restrict__ bias) {
    extern __shared__ __align__(128) unsigned char sm[];
    u32 sb = smem_u32(sm);
    const int tid = threadIdx.x, w = tid >> 5, lane = tid & 31;
    const int n0 = blockIdx.x * 128, m0 = blockIdx.y * 128;
    const int mw = (w & 1) * 64, nw = (w >> 1) * 32;

    const __nv_bfloat16* Asrc[3] = {g_A_hi, g_A_hi, g_A_lo};
    const __nv_bfloat16* Bsrc[3] = {g_W_hi, g_W_lo, g_W_hi};

    auto stage = [&](int kc, int buf) {
        int term = kc >> 3, ksub = (kc & 7) * 64;
        const __nv_bfloat16* As = Asrc[term];
        const __nv_bfloat16* Bs = Bsrc[term];
        u32 ga = sb + GA_OFF(buf), gb = sb + GB_OFF(buf);
#pragma unroll
        for (int it = 0; it < 4; ++it) {  // A: 128 rows x 8 chunks
            int idx = it * 256 + tid;
            int r = idx >> 3, c = idx & 7;
            CP16(ga + r * 144 + c * 16, As + ((size_t)(m0 + r)) * 512 + ksub + c * 8);
        }
#pragma unroll
        for (int it = 0; it < 4; ++it) {  // B: 64 rows x 16 chunks
            int idx = it * 256 + tid;
            int r = idx >> 4, c = idx & 15;
            CP16(gb + r * 272 + c * 16, Bs + ((size_t)(ksub + r)) * 2048 + n0 + c * 8);
        }
    };

    float acc[2][4][4][4];  // [... wait: mi in 0..3 for m64] -> use [4][4][4]
    // (flatten: 4 m16-tiles x 4 n8-tiles x 4 regs)
    float* accp = &acc[0][0][0][0];
#pragma unroll
    for (int i = 0; i < 64; ++i) accp[i] = 0.f;

    stage(0, 0);
    CPCOMMIT();
    int buf = 0;
    for (int kc = 0; kc < 24; ++kc) {
        if (kc + 1 < 24) { stage(kc + 1, buf ^ 1); CPCOMMIT(); CPWAIT1(); }
        else             { CPWAIT0(); }
        __syncthreads();
        u32 ga = sb + GA_OFF(buf), gb = sb + GB_OFF(buf);
#pragma unroll
        for (int kk = 0; kk < 4; ++kk) {
            int k0 = kk * 16;
            u32 af[4][4];
#pragma unroll
            for (int mi = 0; mi < 4; ++mi) {
                u32 a = ga + (mw + mi * 16 + (lane & 15)) * 144 + (k0 + ((lane >> 4) << 3)) * 2;
                ldsm4(af[mi][0], af[mi][1], af[mi][2], af[mi][3], a);
            }
            u32 bf[4][2];
#pragma unroll
            for (int nh = 0; nh < 2; ++nh) {
                u32 a = gb + (k0 + (lane & 7) + ((lane & 8) ? 8 : 0)) * 272 +
                        (nw + nh * 16 + ((lane & 16) ? 8 : 0)) * 2;
                u32 r0, r1, r2, r3;
                ldsm4t(r0, r1, r2, r3, a);
                bf[nh * 2][0] = r0; bf[nh * 2][1] = r1;
                bf[nh * 2 + 1][0] = r2; bf[nh * 2 + 1][1] = r3;
            }
#pragma unroll
            for (int mi = 0; mi < 4; ++mi)
#pragma unroll
                for (int ni = 0; ni < 4; ++ni)
                    mma_bf16(&accp[(mi * 4 + ni) * 4], af[mi], bf[ni]);
        }
        __syncthreads();
        buf ^= 1;
    }

    // epilogue: fragment -> g_xW + bias
#pragma unroll
    for (int mi = 0; mi < 4; ++mi) {
#pragma unroll
        for (int ni = 0; ni < 4; ++ni) {
            float* c = &accp[(mi * 4 + ni) * 4];
            int gm = m0 + mw + mi * 16 + (lane >> 2);
            int gn = n0 + nw + ni * 8 + (lane & 3) * 2;
            float b0 = __ldg(bias + gn), b1 = __ldg(bias + gn + 1);
            *(float2*)(g_xW + (size_t)gm * 2048 + gn) = make_float2(c[0] + b0, c[1] + b1);
            *(float2*)(g_xW + (size_t)(gm + 8) * 2048 + gn) = make_float2(c[2] + b0, c[3] + b1);
        }
    }
}

// ---------------- persistent recurrence (split-bf16 HMMA) ----------------
// 64 CTAs, 256 threads. CTA j owns n-cols [j*8, j*8+8) per gate (32 z-cols).
// SMEM: h hi/lo [b=64][k=512] stride 520 elems; U hi/lo [k=512][n=32] stride 40 elems.
#define RS_AHH 0
#define RS_AHL 66560
#define RS_UH  133120
#define RS_UL  174080
#define RS_Z   215040
#define RS_C   223744
#define RS_TOTAL 225792

__global__ void __launch_bounds__(256) k_lstm(const float* __restrict__ Ug, int layer) {
    extern __shared__ __align__(128) unsigned char sm[];
    u32 sb = smem_u32(sm);
    const int tid = threadIdx.x, w = tid >> 5, lane = tid & 31;
    const int j = blockIdx.x;

    // stage U splits once: [k][r], r = gate*8+nn
    for (int it = 0; it < 64; ++it) {
        int idx = it * 256 + tid;
        int k = idx >> 5, r = idx & 31;
        int col = (r >> 3) * 512 + j * 8 + (r & 7);
        float f = __ldg(Ug + (size_t)k * 2048 + col);
        __nv_bfloat16 hi = __float2bfloat16_rn(f);
        __nv_bfloat16 lo = __float2bfloat16_rn(f - __bfloat162float(hi));
        *(__nv_bfloat16*)(sm + RS_UH + k * 80 + r * 2) = hi;
        *(__nv_bfloat16*)(sm + RS_UL + k * 80 + r * 2) = lo;
    }
    float* cs = (float*)(sm + RS_C);
    cs[tid] = 0.f;
    cs[tid + 256] = 0.f;
    __syncthreads();

    const int r0 = (w & 3) * 16;        // m16 tile
    const int n0 = (w >> 2) * 16;       // n16 half (2 n8 tiles)
    float* zs = (float*)(sm + RS_Z);    // [64][34]

    for (int t = 0; t < Tt; ++t) {
        // prefetch xW for gate phase (overlaps staging latency)
        float xw[2][4];
#pragma unroll
        for (int q = 0; q < 2; ++q) {
            int p = tid + q * 256;
            int b = p & 63, nn = p >> 6;
            const float* base = g_xW + ((size_t)(t * 64 + b)) * 2048 + j * 8 + nn;
#pragma unroll
            for (int g = 0; g < 4; ++g) xw[q][g] = __ldg(base + g * 512);
        }
        // stage h hi/lo [b][k]
        for (int it = 0; it < 32; ++it) {
            int idx = it * 256 + tid;
            int arr = idx >> 12, rem = idx & 4095;
            int row = rem >> 6, c = rem & 63;
            uint4 v = __ldcg((const uint4*)((arr ? g_h_lo : g_h_hi) + row * 512 + c * 8));
            *(uint4*)(sm + (arr ? RS_AHL : RS_AHH) + row * 1040 + c * 16) = v;
        }
        __syncthreads();

        float acc[2][4];
#pragma unroll
        for (int i = 0; i < 2; ++i)
#pragma unroll
            for (int q = 0; q < 4; ++q) acc[i][q] = 0.f;

#pragma unroll 4
        for (int kk = 0; kk < 32; ++kk) {
            int k0 = kk * 16;
            u32 arow = (r0 + (lane & 15)) * 1040 + (k0 + ((lane >> 4) << 3)) * 2;
            u32 ah[4], al[4];
            ldsm4(ah[0], ah[1], ah[2], ah[3], sb + RS_AHH + arow);
            ldsm4(al[0], al[1], al[2], al[3], sb + RS_AHL + arow);
            u32 brow = (k0 + (lane & 7) + ((lane & 8) ? 8 : 0)) * 80 +
                       (n0 + ((lane & 16) ? 8 : 0)) * 2;
            u32 bh[4], bl[4];
            ldsm4t(bh[0], bh[1], bh[2], bh[3], sb + RS_UH + brow);
            ldsm4t(bl[0], bl[1], bl[2], bl[3], sb + RS_UL + brow);
            mma_bf16(acc[0], ah, bh);      // hh @ Uh  (n8 tile 0: regs bh[0],bh[1])
            mma_bf16(acc[1], ah, bh + 2);  //          (n8 tile 1: bh[2],bh[3])
            mma_bf16(acc[0], ah, bl);      // hh @ Ul
            mma_bf16(acc[1], ah, bl + 2);
            mma_bf16(acc[0], al, bh);      // hl @ Uh
            mma_bf16(acc[1], al, bh + 2);
        }
        // fragments -> z smem
#pragma unroll
        for (int ni = 0; ni < 2; ++ni) {
            int col = n0 + ni * 8 + (lane & 3) * 2;
            int row = r0 + (lane >> 2);
            zs[row * 34 + col] = acc[ni][0];
            zs[row * 34 + col + 1] = acc[ni][1];
            zs[(row + 8) * 34 + col] = acc[ni][2];
            zs[(row + 8) * 34 + col + 1] = acc[ni][3];
        }
        __syncthreads();

        // gate math: 2 (b,nn) pairs per thread
#pragma unroll
        for (int q = 0; q < 2; ++q) {
            int p = tid + q * 256;
            int b = p & 63, nn = p >> 6;
            float zi = zs[b * 34 + nn] + xw[q][0];
            float zf = zs[b * 34 + 8 + nn] + xw[q][1];
            float zg = zs[b * 34 + 16 + nn] + xw[q][2];
            float zo = zs[b * 34 + 24 + nn] + xw[q][3];
            float c = sigmf(zf) * cs[p] + sigmf(zi) * tanhf(zg);
            cs[p] = c;
            float hh = sigmf(zo) * tanhf(c);
            __nv_bfloat16 hb = __float2bfloat16_rn(hh);
            __nv_bfloat16 lb = __float2bfloat16_rn(hh - __bfloat162float(hb));
            int hcol = j * 8 + nn;
            g_h_hi[b * 512 + hcol] = hb;
            g_h_lo[b * 512 + hcol] = lb;
            size_t io = ((size_t)(t * 64 + b)) * 512 + hcol;
            if (layer == 0) g_inp[io] = hh;
            else            g_inp[io] += hh;
            if (layer == 0 && t == Tt - 1) g_firsth[(size_t)b * 512 + hcol] = hh;
        }

        // grid barrier (proven monotonic-counter scheme)
        __threadfence();
        __syncthreads();
        if (tid == 0) {
            atomicAdd(&g_bar, 1u);
            unsigned target = (unsigned)(t + 1) * NCTA_R;
            while (*((volatile unsigned*)&g_bar) < target) { }
            __threadfence();
        }
        __syncthreads();
    }
}

// ---------------- launch ----------------
extern "C" void kernel_launch(void* const* d_in, const int* in_sizes, int n_in,
                              void* d_out, int out_size) {
    const float* x    = (const float*)d_in[0];
    const float* W    = (const float*)d_in[1];
    const float* U    = (const float*)d_in[2];
    const float* bias = (const float*)d_in[3];
    float* out = (float*)d_out;

    cudaFuncSetAttribute(k_gemm_tc, cudaFuncAttributeMaxDynamicSharedMemorySize, GEMM_SMEM);
    cudaFuncSetAttribute(k_lstm,    cudaFuncAttributeMaxDynamicSharedMemorySize, RS_TOTAL);

    k_transpose_in<<<dim3(Tt, Bx), 128>>>(x);

    for (int l = 0; l < 4; ++l) {
        k_init<<<16, 256>>>();
        k_split_inp<<<8192, 256>>>();
        k_split_W<<<512, 256>>>(W + (size_t)l * Hh * Gg);
        k_gemm_tc<<<dim3(16, 256), 256, GEMM_SMEM>>>(bias + (size_t)l * Gg);
        k_lstm<<<NCTA_R, 256, RS_TOTAL>>>(U + (size_t)l * Hh * Gg, l);
    }

    k_output<<<dim3(Tt, Bx), 128>>>(out);
    k_states<<<Bx, 128>>>(out);
}

// round 7
// speedup vs baseline: 1.1094x; 1.0020x over previous
#include <cuda_runtime.h>
#include <cuda_bf16.h>
#include <math.h>

typedef unsigned int u32;
typedef unsigned long long u64;

#define Bx 64
#define Tt 512
#define Hh 512
#define Gg 2048
#define NCTA_R 64

// ---------------- device scratch ----------------
__device__ float g_inp[Tt * Bx * Hh];          // [t][b][h] layer input / residual accumulator
__device__ float g_xW[Tt * Bx * Gg];           // [t][b][4H]
__device__ __nv_bfloat16 g_A_hi[Tt * Bx * Hh]; // split of g_inp
__device__ __nv_bfloat16 g_A_lo[Tt * Bx * Hh];
__device__ __nv_bfloat16 g_W_hi[Hh * Gg];      // split of W (natural [k][n])
__device__ __nv_bfloat16 g_W_lo[Hh * Gg];
__device__ __nv_bfloat16 g_h_hi[Bx * Hh];      // h split, [b][k]
__device__ __nv_bfloat16 g_h_lo[Bx * Hh];
__device__ float g_firsth[Bx * Hh];
__device__ unsigned g_bar;

// ---------------- helpers ----------------
__device__ __forceinline__ u32 smem_u32(const void* p) {
    u32 a;
    asm("{ .reg .u64 t; cvta.to.shared.u64 t, %1; cvt.u32.u64 %0, t; }" : "=r"(a) : "l"(p));
    return a;
}
__device__ __forceinline__ void ldsm4(u32& r0, u32& r1, u32& r2, u32& r3, u32 a) {
    asm volatile("ldmatrix.sync.aligned.m8n8.x4.shared.b16 {%0,%1,%2,%3}, [%4];"
                 : "=r"(r0), "=r"(r1), "=r"(r2), "=r"(r3) : "r"(a));
}
__device__ __forceinline__ void ldsm4t(u32& r0, u32& r1, u32& r2, u32& r3, u32 a) {
    asm volatile("ldmatrix.sync.aligned.m8n8.x4.trans.shared.b16 {%0,%1,%2,%3}, [%4];"
                 : "=r"(r0), "=r"(r1), "=r"(r2), "=r"(r3) : "r"(a));
}
__device__ __forceinline__ void mma_bf16(float* c, const u32* a, const u32* b) {
    asm volatile("mma.sync.aligned.m16n8k16.row.col.f32.bf16.bf16.f32 "
                 "{%0,%1,%2,%3}, {%4,%5,%6,%7}, {%8,%9}, {%0,%1,%2,%3};"
                 : "+f"(c[0]), "+f"(c[1]), "+f"(c[2]), "+f"(c[3])
                 : "r"(a[0]), "r"(a[1]), "r"(a[2]), "r"(a[3]), "r"(b[0]), "r"(b[1]));
}
#define CP16(dst, src) asm volatile("cp.async.cg.shared.global [%0], [%1], 16;" :: "r"(dst), "l"(src) : "memory")
#define CPCOMMIT()     asm volatile("cp.async.commit_group;" ::: "memory")
#define CPWAIT0()      asm volatile("cp.async.wait_group 0;" ::: "memory")
#define CPWAIT1()      asm volatile("cp.async.wait_group 1;" ::: "memory")

__device__ __forceinline__ float sigmf(float x) { return 1.f / (1.f + __expf(-x)); }

__device__ __forceinline__ void split8(float4 f0, float4 f1, uint4& hv, uint4& lv) {
    float f[8] = {f0.x, f0.y, f0.z, f0.w, f1.x, f1.y, f1.z, f1.w};
    __nv_bfloat16 h[8], l[8];
#pragma unroll
    for (int i = 0; i < 8; ++i) {
        h[i] = __float2bfloat16_rn(f[i]);
        l[i] = __float2bfloat16_rn(f[i] - __bfloat162float(h[i]));
    }
    hv = *reinterpret_cast<uint4*>(h);
    lv = *reinterpret_cast<uint4*>(l);
}

// ---------------- transpose / output / states / init / splits ----------------
__global__ void k_transpose_in(const float* __restrict__ x) {
    int t = blockIdx.x, b = blockIdx.y;
    const float4* src = (const float4*)(x + ((size_t)b * Tt + t) * Hh);
    float4* dst = (float4*)(g_inp + ((size_t)t * Bx + b) * Hh);
    dst[threadIdx.x] = src[threadIdx.x];
}
__global__ void k_output(float* __restrict__ out) {
    int t = blockIdx.x, b = blockIdx.y;
    const float4* src = (const float4*)(g_inp + ((size_t)t * Bx + b) * Hh);
    float4* dst = (float4*)(out + ((size_t)b * Tt + t) * Hh);
    dst[threadIdx.x] = src[threadIdx.x];
}
__global__ void k_states(float* __restrict__ out) {
    int b = blockIdx.x;
    float4 v = ((const float4*)(g_firsth + (size_t)b * Hh))[threadIdx.x];
    size_t base = (size_t)Bx * Tt * Hh;
#pragma unroll
    for (int l = 0; l < 4; ++l)
        ((float4*)(out + base + ((size_t)l * Bx + b) * Hh))[threadIdx.x] = v;
}
__global__ void k_init() {
    if (blockIdx.x == 0 && threadIdx.x == 0) g_bar = 0u;
    int idx = blockIdx.x * 256 + threadIdx.x;  // 4096 uint4 per array
    ((uint4*)g_h_hi)[idx] = make_uint4(0, 0, 0, 0);
    ((uint4*)g_h_lo)[idx] = make_uint4(0, 0, 0, 0);
}
__global__ void k_split_inp() {
    size_t i8 = ((size_t)blockIdx.x * 256 + threadIdx.x) * 8;
    float4 f0 = *(const float4*)(g_inp + i8);
    float4 f1 = *(const float4*)(g_inp + i8 + 4);
    uint4 hv, lv;
    split8(f0, f1, hv, lv);
    *(uint4*)(g_A_hi + i8) = hv;
    *(uint4*)(g_A_lo + i8) = lv;
}
__global__ void k_split_W(const float* __restrict__ Wl) {
    size_t i8 = ((size_t)blockIdx.x * 256 + threadIdx.x) * 8;
    float4 f0 = __ldg((const float4*)(Wl + i8));
    float4 f1 = __ldg((const float4*)(Wl + i8 + 4));
    uint4 hv, lv;
    split8(f0, f1, hv, lv);
    *(uint4*)(g_W_hi + i8) = hv;
    *(uint4*)(g_W_lo + i8) = lv;
}

// ---------------- input GEMM: g_xW = g_inp @ W + bias (split-bf16 HMMA) ----------------
// BM=128, BN=128, BK=64, virtual K = 1536 (Ah@Wh, Ah@Wl, Al@Wh).
// 8 warps = 2(m64) x 4(n32). Double-buffered cp.async staging.
// SMEM: A stage 128 rows x 72 elems (144B), B stage 64 rows x 136 elems (272B).
#define GA_OFF(buf) ((buf) * 18432)
#define GB_OFF(buf) (36864 + (buf) * 17408)
#define GEMM_SMEM 71680

__global__ void __launch_bounds__(256) k_gemm_tc(const float* __restrict__ bias) {
    extern __shared__ __align__(128) unsigned char sm[];
    u32 sb = smem_u32(sm);
    const int tid = threadIdx.x, w = tid >> 5, lane = tid & 31;
    const int n0 = blockIdx.x * 128, m0 = blockIdx.y * 128;
    const int mw = (w & 1) * 64, nw = (w >> 1) * 32;

    const __nv_bfloat16* Asrc[3] = {g_A_hi, g_A_hi, g_A_lo};
    const __nv_bfloat16* Bsrc[3] = {g_W_hi, g_W_lo, g_W_hi};

    auto stage = [&](int kc, int buf) {
        int term = kc >> 3, ksub = (kc & 7) * 64;
        const __nv_bfloat16* As = Asrc[term];
        const __nv_bfloat16* Bs = Bsrc[term];
        u32 ga = sb + GA_OFF(buf), gb = sb + GB_OFF(buf);
#pragma unroll
        for (int it = 0; it < 4; ++it) {  // A: 128 rows x 8 chunks
            int idx = it * 256 + tid;
            int r = idx >> 3, c = idx & 7;
            CP16(ga + r * 144 + c * 16, As + ((size_t)(m0 + r)) * 512 + ksub + c * 8);
        }
#pragma unroll
        for (int it = 0; it < 4; ++it) {  // B: 64 rows x 16 chunks
            int idx = it * 256 + tid;
            int r = idx >> 4, c = idx & 15;
            CP16(gb + r * 272 + c * 16, Bs + ((size_t)(ksub + r)) * 2048 + n0 + c * 8);
        }
    };

    float acc[2][4][4][4];  // [... wait: mi in 0..3 for m64] -> use [4][4][4]
    // (flatten: 4 m16-tiles x 4 n8-tiles x 4 regs)
    float* accp = &acc[0][0][0][0];
#pragma unroll
    for (int i = 0; i < 64; ++i) accp[i] = 0.f;

    stage(0, 0);
    CPCOMMIT();
    int buf = 0;
    for (int kc = 0; kc < 24; ++kc) {
        if (kc + 1 < 24) { stage(kc + 1, buf ^ 1); CPCOMMIT(); CPWAIT1(); }
        else             { CPWAIT0(); }
        __syncthreads();
        u32 ga = sb + GA_OFF(buf), gb = sb + GB_OFF(buf);
#pragma unroll
        for (int kk = 0; kk < 4; ++kk) {
            int k0 = kk * 16;
            u32 af[4][4];
#pragma unroll
            for (int mi = 0; mi < 4; ++mi) {
                u32 a = ga + (mw + mi * 16 + (lane & 15)) * 144 + (k0 + ((lane >> 4) << 3)) * 2;
                ldsm4(af[mi][0], af[mi][1], af[mi][2], af[mi][3], a);
            }
            u32 bf[4][2];
#pragma unroll
            for (int nh = 0; nh < 2; ++nh) {
                u32 a = gb + (k0 + (lane & 7) + ((lane & 8) ? 8 : 0)) * 272 +
                        (nw + nh * 16 + ((lane & 16) ? 8 : 0)) * 2;
                u32 r0, r1, r2, r3;
                ldsm4t(r0, r1, r2, r3, a);
                bf[nh * 2][0] = r0; bf[nh * 2][1] = r1;
                bf[nh * 2 + 1][0] = r2; bf[nh * 2 + 1][1] = r3;
            }
#pragma unroll
            for (int mi = 0; mi < 4; ++mi)
#pragma unroll
                for (int ni = 0; ni < 4; ++ni)
                    mma_bf16(&accp[(mi * 4 + ni) * 4], af[mi], bf[ni]);
        }
        __syncthreads();
        buf ^= 1;
    }

    // epilogue: fragment -> g_xW + bias
#pragma unroll
    for (int mi = 0; mi < 4; ++mi) {
#pragma unroll
        for (int ni = 0; ni < 4; ++ni) {
            float* c = &accp[(mi * 4 + ni) * 4];
            int gm = m0 + mw + mi * 16 + (lane >> 2);
            int gn = n0 + nw + ni * 8 + (lane & 3) * 2;
            float b0 = __ldg(bias + gn), b1 = __ldg(bias + gn + 1);
            *(float2*)(g_xW + (size_t)gm * 2048 + gn) = make_float2(c[0] + b0, c[1] + b1);
            *(float2*)(g_xW + (size_t)(gm + 8) * 2048 + gn) = make_float2(c[2] + b0, c[3] + b1);
        }
    }
}

// ---------------- persistent recurrence (split-bf16 HMMA) ----------------
// 64 CTAs, 256 threads. CTA j owns n-cols [j*8, j*8+8) per gate (32 z-cols).
// SMEM: h hi/lo [b=64][k=512] stride 520 elems; U hi/lo [k=512][n=32] stride 40 elems.
#define RS_AHH 0
#define RS_AHL 66560
#define RS_UH  133120
#define RS_UL  174080
#define RS_Z   215040
#define RS_C   223744
#define RS_TOTAL 225792

__global__ void __launch_bounds__(256) k_lstm(const float* __restrict__ Ug, int layer) {
    extern __shared__ __align__(128) unsigned char sm[];
    u32 sb = smem_u32(sm);
    const int tid = threadIdx.x, w = tid >> 5, lane = tid & 31;
    const int j = blockIdx.x;

    // stage U splits once: [k][r], r = gate*8+nn
    for (int it = 0; it < 64; ++it) {
        int idx = it * 256 + tid;
        int k = idx >> 5, r = idx & 31;
        int col = (r >> 3) * 512 + j * 8 + (r & 7);
        float f = __ldg(Ug + (size_t)k * 2048 + col);
        __nv_bfloat16 hi = __float2bfloat16_rn(f);
        __nv_bfloat16 lo = __float2bfloat16_rn(f - __bfloat162float(hi));
        *(__nv_bfloat16*)(sm + RS_UH + k * 80 + r * 2) = hi;
        *(__nv_bfloat16*)(sm + RS_UL + k * 80 + r * 2) = lo;
    }
    float* cs = (float*)(sm + RS_C);
    cs[tid] = 0.f;
    cs[tid + 256] = 0.f;
    __syncthreads();

    const int r0 = (w & 3) * 16;        // m16 tile
    const int n0 = (w >> 2) * 16;       // n16 half (2 n8 tiles)
    float* zs = (float*)(sm + RS_Z);    // [64][34]

    for (int t = 0; t < Tt; ++t) {
        // prefetch xW for gate phase (overlaps staging latency)
        float xw[2][4];
#pragma unroll
        for (int q = 0; q < 2; ++q) {
            int p = tid + q * 256;
            int b = p & 63, nn = p >> 6;
            const float* base = g_xW + ((size_t)(t * 64 + b)) * 2048 + j * 8 + nn;
#pragma unroll
            for (int g = 0; g < 4; ++g) xw[q][g] = __ldg(base + g * 512);
        }
        // stage h hi/lo [b][k]
        for (int it = 0; it < 32; ++it) {
            int idx = it * 256 + tid;
            int arr = idx >> 12, rem = idx & 4095;
            int row = rem >> 6, c = rem & 63;
            uint4 v = __ldcg((const uint4*)((arr ? g_h_lo : g_h_hi) + row * 512 + c * 8));
            *(uint4*)(sm + (arr ? RS_AHL : RS_AHH) + row * 1040 + c * 16) = v;
        }
        __syncthreads();

        float acc[2][4];
#pragma unroll
        for (int i = 0; i < 2; ++i)
#pragma unroll
            for (int q = 0; q < 4; ++q) acc[i][q] = 0.f;

#pragma unroll 4
        for (int kk = 0; kk < 32; ++kk) {
            int k0 = kk * 16;
            u32 arow = (r0 + (lane & 15)) * 1040 + (k0 + ((lane >> 4) << 3)) * 2;
            u32 ah[4], al[4];
            ldsm4(ah[0], ah[1], ah[2], ah[3], sb + RS_AHH + arow);
            ldsm4(al[0], al[1], al[2], al[3], sb + RS_AHL + arow);
            u32 brow = (k0 + (lane & 7) + ((lane & 8) ? 8 : 0)) * 80 +
                       (n0 + ((lane & 16) ? 8 : 0)) * 2;
            u32 bh[4], bl[4];
            ldsm4t(bh[0], bh[1], bh[2], bh[3], sb + RS_UH + brow);
            ldsm4t(bl[0], bl[1], bl[2], bl[3], sb + RS_UL + brow);
            mma_bf16(acc[0], ah, bh);      // hh @ Uh  (n8 tile 0: regs bh[0],bh[1])
            mma_bf16(acc[1], ah, bh + 2);  //          (n8 tile 1: bh[2],bh[3])
            mma_bf16(acc[0], ah, bl);      // hh @ Ul
            mma_bf16(acc[1], ah, bl + 2);
            mma_bf16(acc[0], al, bh);      // hl @ Uh
            mma_bf16(acc[1], al, bh + 2);
        }
        // fragments -> z smem
#pragma unroll
        for (int ni = 0; ni < 2; ++ni) {
            int col = n0 + ni * 8 + (lane & 3) * 2;
            int row = r0 + (lane >> 2);
            zs[row * 34 + col] = acc[ni][0];
            zs[row * 34 + col + 1] = acc[ni][1];
            zs[(row + 8) * 34 + col] = acc[ni][2];
            zs[(row + 8) * 34 + col + 1] = acc[ni][3];
        }
        __syncthreads();

        // gate math: 2 (b,nn) pairs per thread
#pragma unroll
        for (int q = 0; q < 2; ++q) {
            int p = tid + q * 256;
            int b = p & 63, nn = p >> 6;
            float zi = zs[b * 34 + nn] + xw[q][0];
            float zf = zs[b * 34 + 8 + nn] + xw[q][1];
            float zg = zs[b * 34 + 16 + nn] + xw[q][2];
            float zo = zs[b * 34 + 24 + nn] + xw[q][3];
            float c = sigmf(zf) * cs[p] + sigmf(zi) * tanhf(zg);
            cs[p] = c;
            float hh = sigmf(zo) * tanhf(c);
            __nv_bfloat16 hb = __float2bfloat16_rn(hh);
            __nv_bfloat16 lb = __float2bfloat16_rn(hh - __bfloat162float(hb));
            int hcol = j * 8 + nn;
            g_h_hi[b * 512 + hcol] = hb;
            g_h_lo[b * 512 + hcol] = lb;
            size_t io = ((size_t)(t * 64 + b)) * 512 + hcol;
            if (layer == 0) g_inp[io] = hh;
            else            g_inp[io] += hh;
            if (layer == 0 && t == Tt - 1) g_firsth[(size_t)b * 512 + hcol] = hh;
        }

        // grid barrier (proven monotonic-counter scheme)
        __threadfence();
        __syncthreads();
        if (tid == 0) {
            atomicAdd(&g_bar, 1u);
            unsigned target = (unsigned)(t + 1) * NCTA_R;
            while (*((volatile unsigned*)&g_bar) < target) { }
            __threadfence();
        }
        __syncthreads();
    }
}

// ---------------- launch ----------------
extern "C" void kernel_launch(void* const* d_in, const int* in_sizes, int n_in,
                              void* d_out, int out_size) {
    const float* x    = (const float*)d_in[0];
    const float* W    = (const float*)d_in[1];
    const float* U    = (const float*)d_in[2];
    const float* bias = (const float*)d_in[3];
    float* out = (float*)d_out;

    cudaFuncSetAttribute(k_gemm_tc, cudaFuncAttributeMaxDynamicSharedMemorySize, GEMM_SMEM);
    cudaFuncSetAttribute(k_lstm,    cudaFuncAttributeMaxDynamicSharedMemorySize, RS_TOTAL);

    k_transpose_in<<<dim3(Tt, Bx), 128>>>(x);

    for (int l = 0; l < 4; ++l) {
        k_init<<<16, 256>>>();
        k_split_inp<<<8192, 256>>>();
        k_split_W<<<512, 256>>>(W + (size_t)l * Hh * Gg);
        k_gemm_tc<<<dim3(16, 256), 256, GEMM_SMEM>>>(bias + (size_t)l * Gg);
        k_lstm<<<NCTA_R, 256, RS_TOTAL>>>(U + (size_t)l * Hh * Gg, l);
    }

    k_output<<<dim3(Tt, Bx), 128>>>(out);
    k_states<<<Bx, 128>>>(out);
}

// round 8
// speedup vs baseline: 2.3025x; 2.0753x over previous
#include <cuda_runtime.h>
#include <cuda_bf16.h>
#include <math.h>

typedef unsigned int u32;
typedef unsigned long long u64;

#define Bx 64
#define Tt 512
#define Hh 512
#define Gg 2048
#define TBH (Tt * Bx * Hh)
#define MAT 9216                       // one 64x64 bf16 matrix, 144B row stride
#define BUFB (8 * MAT)                 // 8 matrices per chunk buffer
#define SM_ZS (2 * BUFB)               // 147456
#define SM_BIAS (SM_ZS + 64 * 68 * 4)  // 164864
#define SM_TOTAL (SM_BIAS + 256)       // 165120

// ---------------- device scratch ----------------
__device__ __nv_bfloat16 g_xh[4][TBH], g_xl[4][TBH];      // layer-input splits [t][b][k]
__device__ __nv_bfloat16 g_Wh[4][Hh * Gg], g_Wl[4][Hh * Gg];
__device__ __nv_bfloat16 g_Uh[4][Hh * Gg], g_Ul[4][Hh * Gg];
__device__ __nv_bfloat16 g_hh[4][2][Bx * Hh], g_hl[4][2][Bx * Hh];  // h splits, dbl-buffered
__device__ float g_firsth[Bx * Hh];
__device__ unsigned g_cnt[4];                              // per-group monotonic counters

// ---------------- helpers ----------------
__device__ __forceinline__ u32 smem_u32(const void* p) {
    u32 a;
    asm("{ .reg .u64 t; cvta.to.shared.u64 t, %1; cvt.u32.u64 %0, t; }" : "=r"(a) : "l"(p));
    return a;
}
__device__ __forceinline__ void ldsm4(u32& r0, u32& r1, u32& r2, u32& r3, u32 a) {
    asm volatile("ldmatrix.sync.aligned.m8n8.x4.shared.b16 {%0,%1,%2,%3}, [%4];"
                 : "=r"(r0), "=r"(r1), "=r"(r2), "=r"(r3) : "r"(a));
}
__device__ __forceinline__ void ldsm4t(u32& r0, u32& r1, u32& r2, u32& r3, u32 a) {
    asm volatile("ldmatrix.sync.aligned.m8n8.x4.trans.shared.b16 {%0,%1,%2,%3}, [%4];"
                 : "=r"(r0), "=r"(r1), "=r"(r2), "=r"(r3) : "r"(a));
}
__device__ __forceinline__ void mma_bf16(float* c, const u32* a, const u32* b) {
    asm volatile("mma.sync.aligned.m16n8k16.row.col.f32.bf16.bf16.f32 "
                 "{%0,%1,%2,%3}, {%4,%5,%6,%7}, {%8,%9}, {%0,%1,%2,%3};"
                 : "+f"(c[0]), "+f"(c[1]), "+f"(c[2]), "+f"(c[3])
                 : "r"(a[0]), "r"(a[1]), "r"(a[2]), "r"(a[3]), "r"(b[0]), "r"(b[1]));
}
#define CP16(dst, src) asm volatile("cp.async.cg.shared.global [%0], [%1], 16;" :: "r"(dst), "l"(src) : "memory")
#define CPCOMMIT()     asm volatile("cp.async.commit_group;" ::: "memory")
#define CPWAIT0()      asm volatile("cp.async.wait_group 0;" ::: "memory")
#define CPWAIT1()      asm volatile("cp.async.wait_group 1;" ::: "memory")

__device__ __forceinline__ float sigf(float x) { return 1.f / (1.f + __expf(-x)); }
__device__ __forceinline__ u32 ld_rel(const unsigned* p) {
    u32 v;
    asm volatile("ld.relaxed.gpu.global.u32 %0, [%1];" : "=r"(v) : "l"(p));
    return v;
}
__device__ __forceinline__ void split8(float4 f0, float4 f1, uint4& hv, uint4& lv) {
    float f[8] = {f0.x, f0.y, f0.z, f0.w, f1.x, f1.y, f1.z, f1.w};
    __nv_bfloat16 h[8], l[8];
#pragma unroll
    for (int i = 0; i < 8; ++i) {
        h[i] = __float2bfloat16_rn(f[i]);
        l[i] = __float2bfloat16_rn(f[i] - __bfloat162float(h[i]));
    }
    hv = *reinterpret_cast<uint4*>(h);
    lv = *reinterpret_cast<uint4*>(l);
}

// ---------------- prep / init / states ----------------
__global__ void k_init() {
    if (blockIdx.x == 0 && threadIdx.x < 4) g_cnt[threadIdx.x] = 0u;
    int idx = blockIdx.x * 256 + threadIdx.x;  // 32768 uint4 per array
    ((uint4*)g_hh)[idx] = make_uint4(0, 0, 0, 0);
    ((uint4*)g_hl)[idx] = make_uint4(0, 0, 0, 0);
}
__global__ void k_prep(const float* __restrict__ x) {
    int t = blockIdx.x, b = blockIdx.y, i = threadIdx.x;  // 64 threads, 8 cols each
    const float* src = x + ((size_t)b * Tt + t) * Hh + i * 8;
    float4 f0 = __ldg((const float4*)src), f1 = __ldg((const float4*)(src + 4));
    uint4 hv, lv;
    split8(f0, f1, hv, lv);
    size_t o = ((size_t)t * Bx + b) * Hh + i * 8;
    *(uint4*)(&g_xh[0][o]) = hv;
    *(uint4*)(&g_xl[0][o]) = lv;
}
__global__ void k_splitWU(const float* __restrict__ W, const float* __restrict__ U) {
    int bid = blockIdx.x;
    const float* src;
    __nv_bfloat16 *dh, *dl;
    size_t i8;
    if (bid < 2048) { src = W; dh = &g_Wh[0][0]; dl = &g_Wl[0][0]; i8 = ((size_t)bid * 256 + threadIdx.x) * 8; }
    else            { src = U; dh = &g_Uh[0][0]; dl = &g_Ul[0][0]; i8 = ((size_t)(bid - 2048) * 256 + threadIdx.x) * 8; }
    float4 f0 = __ldg((const float4*)(src + i8)), f1 = __ldg((const float4*)(src + i8 + 4));
    uint4 hv, lv;
    split8(f0, f1, hv, lv);
    *(uint4*)(dh + i8) = hv;
    *(uint4*)(dl + i8) = lv;
}
__global__ void k_states(float* __restrict__ out) {
    int b = blockIdx.x;
    float4 v = ((const float4*)(g_firsth + (size_t)b * Hh))[threadIdx.x];
    size_t base = (size_t)Bx * Tt * Hh;
#pragma unroll
    for (int l = 0; l < 4; ++l)
        ((float4*)(out + base + ((size_t)l * Bx + b) * Hh))[threadIdx.x] = v;
}

// ---------------- wavefront-pipelined fused LSTM ----------------
// 128 CTAs = 4 layer-groups x 32. CTA j of group g owns h-cols [j*16, j*16+16)
// => z-cols gate*16+nn locally. Per step: z = x@W + h@U (+bias), 3-term split-bf16,
// K streamed in 8 x K64 double-buffered cp.async chunks.
__global__ void __launch_bounds__(256) k_wave(const float* __restrict__ bias,
                                              float* __restrict__ out) {
    extern __shared__ __align__(128) unsigned char sm[];
    u32 sb = smem_u32(sm);
    const int tid = threadIdx.x, w = tid >> 5, lane = tid & 31;
    const int g = blockIdx.x >> 5, j = blockIdx.x & 31;
    const int mw = (w & 3) * 16, nw = (w >> 2) * 32;

    float* zs = (float*)(sm + SM_ZS);
    float* bias_s = (float*)(sm + SM_BIAS);
    if (tid < 64)
        bias_s[tid] = __ldg(bias + g * Gg + (tid >> 4) * 512 + j * 16 + (tid & 15));

    const __nv_bfloat16* wh = g_Wh[g] + j * 16;
    const __nv_bfloat16* wl = g_Wl[g] + j * 16;
    const __nv_bfloat16* uh = g_Uh[g] + j * 16;
    const __nv_bfloat16* ul = g_Ul[g] + j * 16;

    float cst[4] = {0.f, 0.f, 0.f, 0.f};

    for (int t = 0; t < Tt; ++t) {
        if (tid == 0) {
            u32 tg = 32u * (u32)t;
            while (ld_rel(&g_cnt[g]) < tg) __nanosleep(64);
            if (g > 0) {
                u32 tg2 = 32u * (u32)(t + 1);
                while (ld_rel(&g_cnt[g - 1]) < tg2) __nanosleep(64);
            }
            asm volatile("fence.acq_rel.gpu;" ::: "memory");
        }
        __syncthreads();

        const __nv_bfloat16* axh = g_xh[g] + (size_t)t * Bx * Hh;
        const __nv_bfloat16* axl = g_xl[g] + (size_t)t * Bx * Hh;
        const __nv_bfloat16* ahh = g_hh[g][(t & 1) ^ 1];
        const __nv_bfloat16* ahl = g_hl[g][(t & 1) ^ 1];

        auto stage = [&](int ch, int buf) {
            u32 base = sb + buf * BUFB;
            int co = ch * 64;
#pragma unroll
            for (int it = 0; it < 2; ++it) {  // A mats: 2 cp16/thread/mat
                int x = it * 256 + tid;
                int r = x >> 3, c = x & 7;
                size_t so = (size_t)r * Hh + co + c * 8;
                u32 d = r * 144 + c * 16;
                CP16(base + d, axh + so);
                CP16(base + MAT + d, axl + so);
                CP16(base + 2 * MAT + d, ahh + so);
                CP16(base + 3 * MAT + d, ahl + so);
            }
#pragma unroll
            for (int it = 0; it < 2; ++it) {  // B mats
                int x = it * 256 + tid;
                int kr = x >> 3, gg2 = (x >> 1) & 3, hf = x & 1;
                size_t so = (size_t)(co + kr) * Gg + gg2 * 512 + hf * 8;
                u32 d = kr * 144 + gg2 * 32 + hf * 16;
                CP16(base + 4 * MAT + d, wh + so);
                CP16(base + 5 * MAT + d, wl + so);
                CP16(base + 6 * MAT + d, uh + so);
                CP16(base + 7 * MAT + d, ul + so);
            }
        };

        float acc[4][4];
#pragma unroll
        for (int a = 0; a < 4; ++a)
#pragma unroll
            for (int q = 0; q < 4; ++q) acc[a][q] = 0.f;

        stage(0, 0);
        CPCOMMIT();
        int buf = 0;
        for (int ch = 0; ch < 8; ++ch) {
            if (ch < 7) { stage(ch + 1, buf ^ 1); CPCOMMIT(); CPWAIT1(); }
            else        { CPWAIT0(); }
            __syncthreads();
            u32 b0 = sb + buf * BUFB;
#pragma unroll
            for (int kk = 0; kk < 4; ++kk) {
                int k0 = kk * 16;
                u32 arow = (mw + (lane & 15)) * 144 + (k0 + ((lane >> 4) << 3)) * 2;
                u32 fxh[4], fxl[4], fhh[4], fhl[4];
                ldsm4(fxh[0], fxh[1], fxh[2], fxh[3], b0 + arow);
                ldsm4(fxl[0], fxl[1], fxl[2], fxl[3], b0 + MAT + arow);
                ldsm4(fhh[0], fhh[1], fhh[2], fhh[3], b0 + 2 * MAT + arow);
                ldsm4(fhl[0], fhl[1], fhl[2], fhl[3], b0 + 3 * MAT + arow);
                u32 brow = (k0 + (lane & 7) + ((lane & 8) ? 8 : 0)) * 144 +
                           (nw + ((lane & 16) ? 8 : 0)) * 2;
                u32 bwh[8], bwl[8], buh[8], bul[8];
                ldsm4t(bwh[0], bwh[1], bwh[2], bwh[3], b0 + 4 * MAT + brow);
                ldsm4t(bwh[4], bwh[5], bwh[6], bwh[7], b0 + 4 * MAT + brow + 32);
                ldsm4t(bwl[0], bwl[1], bwl[2], bwl[3], b0 + 5 * MAT + brow);
                ldsm4t(bwl[4], bwl[5], bwl[6], bwl[7], b0 + 5 * MAT + brow + 32);
                ldsm4t(buh[0], buh[1], buh[2], buh[3], b0 + 6 * MAT + brow);
                ldsm4t(buh[4], buh[5], buh[6], buh[7], b0 + 6 * MAT + brow + 32);
                ldsm4t(bul[0], bul[1], bul[2], bul[3], b0 + 7 * MAT + brow);
                ldsm4t(bul[4], bul[5], bul[6], bul[7], b0 + 7 * MAT + brow + 32);
#pragma unroll
                for (int ni = 0; ni < 4; ++ni) {
                    mma_bf16(acc[ni], fxh, bwh + ni * 2);
                    mma_bf16(acc[ni], fxh, bwl + ni * 2);
                    mma_bf16(acc[ni], fxl, bwh + ni * 2);
                    mma_bf16(acc[ni], fhh, buh + ni * 2);
                    mma_bf16(acc[ni], fhh, bul + ni * 2);
                    mma_bf16(acc[ni], fhl, buh + ni * 2);
                }
            }
            __syncthreads();
            buf ^= 1;
        }

        // fragments -> zs
#pragma unroll
        for (int ni = 0; ni < 4; ++ni) {
            int col = nw + ni * 8 + (lane & 3) * 2;
            int row = mw + (lane >> 2);
            zs[row * 68 + col] = acc[ni][0];
            zs[row * 68 + col + 1] = acc[ni][1];
            zs[(row + 8) * 68 + col] = acc[ni][2];
            zs[(row + 8) * 68 + col + 1] = acc[ni][3];
        }
        __syncthreads();

        // gates: 4 (b, nn) pairs per thread
#pragma unroll
        for (int q = 0; q < 4; ++q) {
            int p = q * 256 + tid;
            int b = p & 63, nn = p >> 6;
            int col = j * 16 + nn;
            float zi = zs[b * 68 + nn] + bias_s[nn];
            float zf = zs[b * 68 + 16 + nn] + bias_s[16 + nn];
            float zg = zs[b * 68 + 32 + nn] + bias_s[32 + nn];
            float zo = zs[b * 68 + 48 + nn] + bias_s[48 + nn];
            float c = sigf(zf) * cst[q] + sigf(zi) * tanhf(zg);
            cst[q] = c;
            float h = sigf(zo) * tanhf(c);
            size_t idx = ((size_t)t * Bx + b) * Hh + col;
            float val = h;
            if (g > 0)
                val += __bfloat162float(g_xh[g][idx]) + __bfloat162float(g_xl[g][idx]);
            __nv_bfloat16 hb = __float2bfloat16_rn(h);
            g_hh[g][t & 1][b * Hh + col] = hb;
            g_hl[g][t & 1][b * Hh + col] = __float2bfloat16_rn(h - __bfloat162float(hb));
            if (g < 3) {
                __nv_bfloat16 vb = __float2bfloat16_rn(val);
                g_xh[g + 1][idx] = vb;
                g_xl[g + 1][idx] = __float2bfloat16_rn(val - __bfloat162float(vb));
            } else {
                out[(size_t)b * Tt * Hh + (size_t)t * Hh + col] = val;
            }
            if (g == 0 && t == Tt - 1) g_firsth[b * Hh + col] = h;
        }
        __syncthreads();
        if (tid == 0) {
            asm volatile("fence.acq_rel.gpu;" ::: "memory");
            atomicAdd(&g_cnt[g], 1u);
        }
    }
}

// ---------------- launch ----------------
extern "C" void kernel_launch(void* const* d_in, const int* in_sizes, int n_in,
                              void* d_out, int out_size) {
    const float* x    = (const float*)d_in[0];
    const float* W    = (const float*)d_in[1];
    const float* U    = (const float*)d_in[2];
    const float* bias = (const float*)d_in[3];
    float* out = (float*)d_out;

    cudaFuncSetAttribute(k_wave, cudaFuncAttributeMaxDynamicSharedMemorySize, SM_TOTAL);

    k_init<<<128, 256>>>();
    k_prep<<<dim3(Tt, Bx), 64>>>(x);
    k_splitWU<<<4096, 256>>>(W, U);
    k_wave<<<128, 256, SM_TOTAL>>>(bias, out);
    k_states<<<Bx, 128>>>(out);
}